// round 5
// baseline (speedup 1.0000x reference)
#include <cuda_runtime.h>

#define NN 100000
#define NE 1600000
#define FIN 256
#define NH 4
#define NC 64

struct __align__(32) SP { float4 a; float4 p; };   // src-side: a_src + p, one 32B sector

// Scratch (static __device__ — no allocations allowed)
__device__ float  d_W[12 * FIN];   // 12 folded weight vectors: [as0..3, ad0..3, p0..3]
__device__ float  d_cb;            // bias . fc_w + fc_b
__device__ SP     d_sp[NN];        // packed a_src + p
__device__ float4 d_ad[NN];        // per-node a_dst
__device__ float4 d_den[NN];       // softmax denominators per head
__device__ float4 d_num[NN];       // weighted numerators per head

// ---------------------------------------------------------------------------
// K1: fold lin_w with (att_src, att_dst, fc_w) into 12 x 256 vectors + cb.
// ---------------------------------------------------------------------------
__global__ void k_pre(const float* __restrict__ lin_w,
                      const float* __restrict__ att_src,
                      const float* __restrict__ att_dst,
                      const float* __restrict__ bias,
                      const float* __restrict__ fc_w,
                      const float* __restrict__ fc_b) {
    const int j = blockIdx.x;
    const int k = threadIdx.x;   // 0..255 (feature dim)
    if (j < 12) {
        const int g = j >> 2;    // 0 = att_src, 1 = att_dst, 2 = fc_w
        const int h = j & 3;
        const float* coef = (g == 0) ? att_src + h * NC
                          : (g == 1) ? att_dst + h * NC
                                     : fc_w   + h * NC;
        const float* lw = lin_w + (size_t)h * NC * FIN + k;
        float acc = 0.f;
#pragma unroll 8
        for (int c = 0; c < NC; ++c)
            acc += coef[c] * lw[(size_t)c * FIN];
        d_W[j * FIN + k] = acc;
    } else {
        __shared__ float red[256];
        red[k] = bias[k] * fc_w[k];
        __syncthreads();
        for (int s = 128; s; s >>= 1) {
            if (k < s) red[k] += red[k + s];
            __syncthreads();
        }
        if (k == 0) d_cb = red[0] + fc_b[0];
    }
}

// ---------------------------------------------------------------------------
// K2: per-node projections, smem-staged, w amortized over 4 nodes per thread.
// Block = 64 threads (2 warps) handles 32 nodes; ~45KB static smem -> 5
// blocks/SM. Lane = (g = lane>>3, s = lane&7); thread computes 4 nodes
// nl0..nl0+3 so each broadcast w-LDS feeds 4 FMAs. f32x2 packed FMA pairs the
// node dimension (x01 = nodes 0,1 / x23 = nodes 2,3).
// Banks: xs stride 258 -> x-LDS banks = 8g + s (all 32 distinct, conflict-
// free); w-LDS is 8 distinct addrs broadcast 4-way (1 phase).
// ---------------------------------------------------------------------------
__global__ void __launch_bounds__(64) k_proj(const float* __restrict__ x) {
    __shared__ float xs[32][258];
    __shared__ float ws[12 * FIN];

    const int tid = threadIdx.x;
    const int nb  = blockIdx.x * 32;
    const int lim = NN - nb;                  // valid rows in this block

    // stage w: 3072 floats / 64 threads = 48 each (coalesced, L2-resident)
#pragma unroll
    for (int i = 0; i < 48; ++i)
        ws[i * 64 + tid] = d_W[i * 64 + tid];

    // stage x: 32 rows x 256 floats, scalar coalesced (conflict-free STS)
#pragma unroll 4
    for (int i = 0; i < 128; ++i) {
        const int f   = i * 64 + tid;
        const int row = f >> 8;
        const int col = f & 255;
        xs[row][col] = (row < lim) ? x[(size_t)(nb + row) * FIN + col] : 0.f;
    }
    __syncthreads();

    const int warp = tid >> 5;
    const int lane = tid & 31;
    const int g    = lane >> 3;
    const int s    = lane & 7;
    const int nl0  = warp * 16 + g * 4;       // first of this thread's 4 nodes

    unsigned long long acc01[12], acc23[12];
#pragma unroll
    for (int j = 0; j < 12; ++j) { acc01[j] = 0ull; acc23[j] = 0ull; }

#pragma unroll 4
    for (int t = 0; t < 32; ++t) {
        const int k = t * 8 + s;
        const float xv0 = xs[nl0 + 0][k];
        const float xv1 = xs[nl0 + 1][k];
        const float xv2 = xs[nl0 + 2][k];
        const float xv3 = xs[nl0 + 3][k];
        unsigned long long x01, x23;
        asm("mov.b64 %0,{%1,%2};" : "=l"(x01) : "f"(xv0), "f"(xv1));
        asm("mov.b64 %0,{%1,%2};" : "=l"(x23) : "f"(xv2), "f"(xv3));
#pragma unroll
        for (int j = 0; j < 12; ++j) {
            const float w = ws[j * FIN + k];
            unsigned long long w2;
            asm("mov.b64 %0,{%1,%1};" : "=l"(w2) : "f"(w));
            asm("fma.rn.f32x2 %0,%1,%2,%0;" : "+l"(acc01[j]) : "l"(x01), "l"(w2));
            asm("fma.rn.f32x2 %0,%1,%2,%0;" : "+l"(acc23[j]) : "l"(x23), "l"(w2));
        }
    }

    // unpack, reduce over s (xor within aligned 8-lane groups), write
    float acc[12][4];
#pragma unroll
    for (int j = 0; j < 12; ++j) {
        asm("mov.b64 {%0,%1},%2;" : "=f"(acc[j][0]), "=f"(acc[j][1]) : "l"(acc01[j]));
        asm("mov.b64 {%0,%1},%2;" : "=f"(acc[j][2]), "=f"(acc[j][3]) : "l"(acc23[j]));
    }
#pragma unroll
    for (int j = 0; j < 12; ++j)
#pragma unroll
        for (int m = 0; m < 4; ++m) {
            acc[j][m] += __shfl_xor_sync(0xffffffffu, acc[j][m], 4);
            acc[j][m] += __shfl_xor_sync(0xffffffffu, acc[j][m], 2);
            acc[j][m] += __shfl_xor_sync(0xffffffffu, acc[j][m], 1);
        }
    if (s == 0) {
#pragma unroll
        for (int m = 0; m < 4; ++m) {
            const int node = nb + nl0 + m;
            if (node < NN) {
                d_sp[node].a = make_float4(acc[0][m], acc[1][m], acc[2][m],  acc[3][m]);
                d_ad[node]   = make_float4(acc[4][m], acc[5][m], acc[6][m],  acc[7][m]);
                d_sp[node].p = make_float4(acc[8][m], acc[9][m], acc[10][m], acc[11][m]);
                d_den[node]  = make_float4(0.f, 0.f, 0.f, 0.f);
                d_num[node]  = make_float4(0.f, 0.f, 0.f, 0.f);
            }
        }
    }
}

// ---------------------------------------------------------------------------
// K3: edge pass, 8 edges/thread, all gathers issued before any compute/RED
// (MLP ~24). src side is one 32B sector (SP pack). Softmax max-subtraction
// skipped (shift-invariant; logits are small). den/num kept in separate
// arrays so the two REDs hash to different L2 slices.
// ---------------------------------------------------------------------------
__global__ void __launch_bounds__(256) k_edge(const int* __restrict__ ei) {
    const int base = (blockIdx.x * 256 + threadIdx.x) * 8;
    if (base >= NE) return;                       // NE % 8 == 0 -> all valid

    int srcs[8], dsts[8];
    {
        const int4 sA = *(const int4*)(ei + base);
        const int4 sB = *(const int4*)(ei + base + 4);
        const int4 dA = *(const int4*)(ei + NE + base);
        const int4 dB = *(const int4*)(ei + NE + base + 4);
        srcs[0]=sA.x; srcs[1]=sA.y; srcs[2]=sA.z; srcs[3]=sA.w;
        srcs[4]=sB.x; srcs[5]=sB.y; srcs[6]=sB.z; srcs[7]=sB.w;
        dsts[0]=dA.x; dsts[1]=dA.y; dsts[2]=dA.z; dsts[3]=dA.w;
        dsts[4]=dB.x; dsts[5]=dB.y; dsts[6]=dB.z; dsts[7]=dB.w;
    }

    float4 a[8], p[8], b[8];
#pragma unroll
    for (int i = 0; i < 8; ++i) { a[i] = d_sp[srcs[i]].a; p[i] = d_sp[srcs[i]].p; }
#pragma unroll
    for (int i = 0; i < 8; ++i) b[i] = d_ad[dsts[i]];

#pragma unroll
    for (int i = 0; i < 8; ++i) {
        float t;
        float4 ex, np;
        t = a[i].x + b[i].x; t = t > 0.f ? t : 0.2f * t; ex.x = __expf(t);
        t = a[i].y + b[i].y; t = t > 0.f ? t : 0.2f * t; ex.y = __expf(t);
        t = a[i].z + b[i].z; t = t > 0.f ? t : 0.2f * t; ex.z = __expf(t);
        t = a[i].w + b[i].w; t = t > 0.f ? t : 0.2f * t; ex.w = __expf(t);
        np.x = ex.x * p[i].x; np.y = ex.y * p[i].y;
        np.z = ex.z * p[i].z; np.w = ex.w * p[i].w;

        asm volatile("red.global.add.v4.f32 [%0], {%1,%2,%3,%4};"
                     :: "l"(&d_den[dsts[i]]), "f"(ex.x), "f"(ex.y), "f"(ex.z), "f"(ex.w)
                     : "memory");
        asm volatile("red.global.add.v4.f32 [%0], {%1,%2,%3,%4};"
                     :: "l"(&d_num[dsts[i]]), "f"(np.x), "f"(np.y), "f"(np.z), "f"(np.w)
                     : "memory");
    }
}

// ---------------------------------------------------------------------------
// K4: finalize. out[n] = cb + sum_h num/(den + 1e-16)
// ---------------------------------------------------------------------------
__global__ void __launch_bounds__(256) k_final(float* __restrict__ out) {
    const int n = blockIdx.x * blockDim.x + threadIdx.x;
    if (n >= NN) return;
    const float4 d = d_den[n];
    const float4 u = d_num[n];
    out[n] = d_cb
           + u.x / (d.x + 1e-16f)
           + u.y / (d.y + 1e-16f)
           + u.z / (d.z + 1e-16f)
           + u.w / (d.w + 1e-16f);
}

extern "C" void kernel_launch(void* const* d_in, const int* in_sizes, int n_in,
                              void* d_out, int out_size) {
    const float* x       = (const float*)d_in[0];
    const int*   ei      = (const int*)d_in[1];
    const float* lin_w   = (const float*)d_in[2];
    const float* att_src = (const float*)d_in[3];
    const float* att_dst = (const float*)d_in[4];
    const float* bias    = (const float*)d_in[5];
    const float* fc_w    = (const float*)d_in[6];
    const float* fc_b    = (const float*)d_in[7];
    float* out = (float*)d_out;

    k_pre  <<<13, 256>>>(lin_w, att_src, att_dst, bias, fc_w, fc_b);
    k_proj <<<(NN + 31) / 32, 64>>>(x);           // 3125 blocks, 32 nodes each
    k_edge <<<(NE / 8 + 255) / 256, 256>>>(ei);   // 8 edges per thread
    k_final<<<(NN + 255) / 256, 256>>>(out);
}

// round 6
// speedup vs baseline: 1.4674x; 1.4674x over previous
#include <cuda_runtime.h>

#define NN 100000
#define NE 1600000
#define FIN 256
#define NH 4
#define NC 64

struct __align__(32) SP { float4 a; float4 p; };   // src-side: a_src + p, one 32B sector

// Scratch (static __device__ — no allocations allowed)
__device__ float  d_W[12 * FIN];   // 12 folded weight vectors: [as0..3, ad0..3, p0..3]
__device__ float  d_cb;            // bias . fc_w + fc_b
__device__ SP     d_sp[NN];        // packed a_src + p
__device__ float4 d_ad[NN];        // per-node a_dst, 4 heads
__device__ float4 d_den[NN];       // softmax denominators per head
__device__ float4 d_num[NN];       // weighted numerators per head

// ---------------------------------------------------------------------------
// K1: fold lin_w with (att_src, att_dst, fc_w) into 12 x 256 vectors + cb.
// ---------------------------------------------------------------------------
__global__ void k_pre(const float* __restrict__ lin_w,
                      const float* __restrict__ att_src,
                      const float* __restrict__ att_dst,
                      const float* __restrict__ bias,
                      const float* __restrict__ fc_w,
                      const float* __restrict__ fc_b) {
    const int j = blockIdx.x;
    const int k = threadIdx.x;   // 0..255 (feature dim)
    if (j < 12) {
        const int g = j >> 2;    // 0 = att_src, 1 = att_dst, 2 = fc_w
        const int h = j & 3;
        const float* coef = (g == 0) ? att_src + h * NC
                          : (g == 1) ? att_dst + h * NC
                                     : fc_w   + h * NC;
        const float* lw = lin_w + (size_t)h * NC * FIN + k;
        float acc = 0.f;
#pragma unroll 8
        for (int c = 0; c < NC; ++c)
            acc += coef[c] * lw[(size_t)c * FIN];
        d_W[j * FIN + k] = acc;
    } else {
        __shared__ float red[256];
        red[k] = bias[k] * fc_w[k];
        __syncthreads();
        for (int s = 128; s; s >>= 1) {
            if (k < s) red[k] += red[k + s];
            __syncthreads();
        }
        if (k == 0) d_cb = red[0] + fc_b[0];
    }
}

// ---------------------------------------------------------------------------
// K2: per-node projections, smem-staged (identical to the 98.3us version
// except the output writes go to the packed SP struct).
// Block = 256 threads handles 32 nodes. Each warp computes 4 nodes; lane =
// (g = node-in-warp, s = k mod 8). Bank math:
//   x:  addr%32 = g*8 + s  (row stride 264, 264%32=8)  -> conflict-free
//   w:  8 consecutive addrs broadcast to 4 lanes each  -> conflict-free
// ---------------------------------------------------------------------------
__global__ void __launch_bounds__(256) k_proj(const float* __restrict__ x) {
    __shared__ float xs[32][264];
    __shared__ float ws[12 * FIN];

    const int tid = threadIdx.x;
    const int nb  = blockIdx.x * 32;

#pragma unroll
    for (int i = 0; i < 12; ++i)
        ws[tid + i * 256] = d_W[tid + i * 256];

#pragma unroll
    for (int i = 0; i < 32; ++i) {
        const int r = (tid >> 8) + i;            // tid>>8 == 0; r = i
        xs[r][tid & 255] = x[(size_t)(nb + r) * FIN + (tid & 255)];
    }
    __syncthreads();

    const int warp = tid >> 5;
    const int lane = tid & 31;
    const int g    = lane >> 3;
    const int s    = lane & 7;
    const int nl   = warp * 4 + g;               // local node 0..31

    float acc[12];
#pragma unroll
    for (int j = 0; j < 12; ++j) acc[j] = 0.f;

    const float* xrow = xs[nl];
#pragma unroll 4
    for (int t = 0; t < 32; ++t) {
        const int k = t * 8 + s;
        const float xv = xrow[k];
#pragma unroll
        for (int j = 0; j < 12; ++j)
            acc[j] += xv * ws[j * 256 + k];
    }
#pragma unroll
    for (int j = 0; j < 12; ++j) {
        acc[j] += __shfl_xor_sync(0xffffffffu, acc[j], 4);
        acc[j] += __shfl_xor_sync(0xffffffffu, acc[j], 2);
        acc[j] += __shfl_xor_sync(0xffffffffu, acc[j], 1);
    }
    if (s == 0) {
        const int node = nb + nl;
        d_sp[node].a = make_float4(acc[0], acc[1], acc[2],  acc[3]);
        d_ad[node]   = make_float4(acc[4], acc[5], acc[6],  acc[7]);
        d_sp[node].p = make_float4(acc[8], acc[9], acc[10], acc[11]);
        d_den[node] = make_float4(0.f, 0.f, 0.f, 0.f);
        d_num[node] = make_float4(0.f, 0.f, 0.f, 0.f);
    }
}

// ---------------------------------------------------------------------------
// K3: edge pass, 4 edges per thread (int4 index loads), identical to the
// 98.3us version except the src gather reads the packed SP struct: one 32B
// sector per src instead of two separate 16B lines.
// ---------------------------------------------------------------------------
__device__ __forceinline__ void edge_one(int dst,
                                         const float4 a, const float4 p) {
    const float4 b = d_ad[dst];
    float t;
    float4 ex, np;
    t = a.x + b.x; t = t > 0.f ? t : 0.2f * t; ex.x = __expf(t);
    t = a.y + b.y; t = t > 0.f ? t : 0.2f * t; ex.y = __expf(t);
    t = a.z + b.z; t = t > 0.f ? t : 0.2f * t; ex.z = __expf(t);
    t = a.w + b.w; t = t > 0.f ? t : 0.2f * t; ex.w = __expf(t);
    np.x = ex.x * p.x; np.y = ex.y * p.y; np.z = ex.z * p.z; np.w = ex.w * p.w;

    asm volatile("red.global.add.v4.f32 [%0], {%1,%2,%3,%4};"
                 :: "l"(&d_den[dst]), "f"(ex.x), "f"(ex.y), "f"(ex.z), "f"(ex.w)
                 : "memory");
    asm volatile("red.global.add.v4.f32 [%0], {%1,%2,%3,%4};"
                 :: "l"(&d_num[dst]), "f"(np.x), "f"(np.y), "f"(np.z), "f"(np.w)
                 : "memory");
}

__global__ void __launch_bounds__(256) k_edge(const int* __restrict__ ei) {
    const int base = (blockIdx.x * 256 + threadIdx.x) * 4;
    if (base >= NE) return;                       // NE % 4 == 0 -> all 4 valid

    const int4 s4 = *(const int4*)(ei + base);
    const int4 d4 = *(const int4*)(ei + NE + base);

    // Issue all src-side gathers up front (one 32B sector per src).
    const float4 a0 = d_sp[s4.x].a, p0 = d_sp[s4.x].p;
    const float4 a1 = d_sp[s4.y].a, p1 = d_sp[s4.y].p;
    const float4 a2 = d_sp[s4.z].a, p2 = d_sp[s4.z].p;
    const float4 a3 = d_sp[s4.w].a, p3 = d_sp[s4.w].p;

    edge_one(d4.x, a0, p0);
    edge_one(d4.y, a1, p1);
    edge_one(d4.z, a2, p2);
    edge_one(d4.w, a3, p3);
}

// ---------------------------------------------------------------------------
// K4: finalize. out[n] = cb + sum_h num/(den + 1e-16)
// ---------------------------------------------------------------------------
__global__ void __launch_bounds__(256) k_final(float* __restrict__ out) {
    const int n = blockIdx.x * blockDim.x + threadIdx.x;
    if (n >= NN) return;
    const float4 d = d_den[n];
    const float4 u = d_num[n];
    out[n] = d_cb
           + u.x / (d.x + 1e-16f)
           + u.y / (d.y + 1e-16f)
           + u.z / (d.z + 1e-16f)
           + u.w / (d.w + 1e-16f);
}

extern "C" void kernel_launch(void* const* d_in, const int* in_sizes, int n_in,
                              void* d_out, int out_size) {
    const float* x       = (const float*)d_in[0];
    const int*   ei      = (const int*)d_in[1];
    const float* lin_w   = (const float*)d_in[2];
    const float* att_src = (const float*)d_in[3];
    const float* att_dst = (const float*)d_in[4];
    const float* bias    = (const float*)d_in[5];
    const float* fc_w    = (const float*)d_in[6];
    const float* fc_b    = (const float*)d_in[7];
    float* out = (float*)d_out;

    k_pre  <<<13, 256>>>(lin_w, att_src, att_dst, bias, fc_w, fc_b);
    k_proj <<<NN / 32, 256>>>(x);                     // 3125 blocks, 32 nodes each
    k_edge <<<(NE / 4 + 255) / 256, 256>>>(ei);       // 4 edges per thread
    k_final<<<(NN + 255) / 256, 256>>>(out);
}

// round 7
// speedup vs baseline: 1.7819x; 1.2143x over previous
#include <cuda_runtime.h>

#define NN 100000
#define NE 1600000
#define FIN 256
#define NH 4
#define NC 64

struct __align__(32) SP { float4 a; float4 p; };   // src-side: a_src + p, one 32B sector

// Scratch (static __device__ — no allocations allowed)
__device__ float  d_W[12 * FIN];   // 12 folded weight vectors: [as0..3, ad0..3, p0..3]
__device__ float  d_cb;            // bias . fc_w + fc_b
__device__ SP     d_sp[NN];        // packed a_src + p
__device__ float4 d_ad[NN];        // per-node a_dst, 4 heads
__device__ float4 d_den[NN];       // softmax denominators per head
__device__ float4 d_num[NN];       // weighted numerators per head

// ---------------------------------------------------------------------------
// K1: fold lin_w with (att_src, att_dst, fc_w) into 12 x 256 vectors + cb.
// ---------------------------------------------------------------------------
__global__ void k_pre(const float* __restrict__ lin_w,
                      const float* __restrict__ att_src,
                      const float* __restrict__ att_dst,
                      const float* __restrict__ bias,
                      const float* __restrict__ fc_w,
                      const float* __restrict__ fc_b) {
    const int j = blockIdx.x;
    const int k = threadIdx.x;   // 0..255 (feature dim)
    if (j < 12) {
        const int g = j >> 2;    // 0 = att_src, 1 = att_dst, 2 = fc_w
        const int h = j & 3;
        const float* coef = (g == 0) ? att_src + h * NC
                          : (g == 1) ? att_dst + h * NC
                                     : fc_w   + h * NC;
        const float* lw = lin_w + (size_t)h * NC * FIN + k;
        float acc = 0.f;
#pragma unroll 8
        for (int c = 0; c < NC; ++c)
            acc += coef[c] * lw[(size_t)c * FIN];
        d_W[j * FIN + k] = acc;
    } else {
        __shared__ float red[256];
        red[k] = bias[k] * fc_w[k];
        __syncthreads();
        for (int s = 128; s; s >>= 1) {
            if (k < s) red[k] += red[k + s];
            __syncthreads();
        }
        if (k == 0) d_cb = red[0] + fc_b[0];
    }
}

// ---------------------------------------------------------------------------
// K2: per-node projections, smem-staged, 2 nodes per thread.
// Block = 128 threads (4 warps) handles 32 nodes. Warp covers 8 nodes;
// lane = (g = lane>>3, s = lane&7); thread computes nodes (wb+g) and (wb+g+4)
// so each broadcast w-LDS feeds 2 FMA pairs -> w crossbar traffic halved.
// Banks (row stride 264, 264%32=8): x addr%32 = 8g+8t+s for node wb+g and
// the same set for wb+g+4 (+32k) -> all 32 banks distinct, conflict-free.
// w-LDS: 8 consecutive addrs broadcast 4-way -> conflict-free.
// Staging uses float4 global loads (16 LDG.128/thread, high MLP).
// ---------------------------------------------------------------------------
__global__ void __launch_bounds__(128) k_proj(const float* __restrict__ x) {
    __shared__ float xs[32][264];
    __shared__ float ws[12 * FIN];

    const int tid = threadIdx.x;
    const int nb  = blockIdx.x * 32;

    // stage w: 3072 floats / 128 threads = 24 each (coalesced)
#pragma unroll
    for (int i = 0; i < 24; ++i)
        ws[tid + i * 128] = d_W[tid + i * 128];

    // stage x: 32 rows x 64 float4 = 2048 float4 / 128 threads = 16 each.
    // row stride 264 floats = 66 float4 (1056 B, 16B-aligned).
    {
        const float4* xg = (const float4*)(x + (size_t)nb * FIN);
#pragma unroll
        for (int i = 0; i < 16; ++i) {
            const int f4  = tid + i * 128;       // 0..2047
            const int row = f4 >> 6;
            const int c4  = f4 & 63;
            ((float4*)&xs[row][c4 * 4])[0] = xg[row * 64 + c4];
        }
    }
    __syncthreads();

    const int warp = tid >> 5;
    const int lane = tid & 31;
    const int g    = lane >> 3;
    const int s    = lane & 7;
    const int wb   = warp * 8;                   // warp's first local node
    const int n0   = wb + g;                     // thread's node A
    const int n1   = wb + g + 4;                 // thread's node B

    float acc0[12], acc1[12];
#pragma unroll
    for (int j = 0; j < 12; ++j) { acc0[j] = 0.f; acc1[j] = 0.f; }

    const float* xr0 = xs[n0];
    const float* xr1 = xs[n1];
#pragma unroll 4
    for (int t = 0; t < 32; ++t) {
        const int k = t * 8 + s;
        const float xv0 = xr0[k];
        const float xv1 = xr1[k];
#pragma unroll
        for (int j = 0; j < 12; ++j) {
            const float w = ws[j * 256 + k];
            acc0[j] += xv0 * w;
            acc1[j] += xv1 * w;
        }
    }
#pragma unroll
    for (int j = 0; j < 12; ++j) {
        acc0[j] += __shfl_xor_sync(0xffffffffu, acc0[j], 4);
        acc0[j] += __shfl_xor_sync(0xffffffffu, acc0[j], 2);
        acc0[j] += __shfl_xor_sync(0xffffffffu, acc0[j], 1);
        acc1[j] += __shfl_xor_sync(0xffffffffu, acc1[j], 4);
        acc1[j] += __shfl_xor_sync(0xffffffffu, acc1[j], 2);
        acc1[j] += __shfl_xor_sync(0xffffffffu, acc1[j], 1);
    }
    if (s == 0) {
        const int nodeA = nb + n0;
        d_sp[nodeA].a = make_float4(acc0[0], acc0[1], acc0[2],  acc0[3]);
        d_ad[nodeA]   = make_float4(acc0[4], acc0[5], acc0[6],  acc0[7]);
        d_sp[nodeA].p = make_float4(acc0[8], acc0[9], acc0[10], acc0[11]);
        d_den[nodeA]  = make_float4(0.f, 0.f, 0.f, 0.f);
        d_num[nodeA]  = make_float4(0.f, 0.f, 0.f, 0.f);

        const int nodeB = nb + n1;
        d_sp[nodeB].a = make_float4(acc1[0], acc1[1], acc1[2],  acc1[3]);
        d_ad[nodeB]   = make_float4(acc1[4], acc1[5], acc1[6],  acc1[7]);
        d_sp[nodeB].p = make_float4(acc1[8], acc1[9], acc1[10], acc1[11]);
        d_den[nodeB]  = make_float4(0.f, 0.f, 0.f, 0.f);
        d_num[nodeB]  = make_float4(0.f, 0.f, 0.f, 0.f);
    }
}

// ---------------------------------------------------------------------------
// K3: edge pass, 4 edges per thread (int4 index loads). Src gather reads the
// packed SP struct (one 32B sector per src). Softmax max-subtraction skipped
// (shift-invariant; logits small). den/num in separate arrays.
// ---------------------------------------------------------------------------
__device__ __forceinline__ void edge_one(int dst,
                                         const float4 a, const float4 p) {
    const float4 b = d_ad[dst];
    float t;
    float4 ex, np;
    t = a.x + b.x; t = t > 0.f ? t : 0.2f * t; ex.x = __expf(t);
    t = a.y + b.y; t = t > 0.f ? t : 0.2f * t; ex.y = __expf(t);
    t = a.z + b.z; t = t > 0.f ? t : 0.2f * t; ex.z = __expf(t);
    t = a.w + b.w; t = t > 0.f ? t : 0.2f * t; ex.w = __expf(t);
    np.x = ex.x * p.x; np.y = ex.y * p.y; np.z = ex.z * p.z; np.w = ex.w * p.w;

    asm volatile("red.global.add.v4.f32 [%0], {%1,%2,%3,%4};"
                 :: "l"(&d_den[dst]), "f"(ex.x), "f"(ex.y), "f"(ex.z), "f"(ex.w)
                 : "memory");
    asm volatile("red.global.add.v4.f32 [%0], {%1,%2,%3,%4};"
                 :: "l"(&d_num[dst]), "f"(np.x), "f"(np.y), "f"(np.z), "f"(np.w)
                 : "memory");
}

__global__ void __launch_bounds__(256) k_edge(const int* __restrict__ ei) {
    const int base = (blockIdx.x * 256 + threadIdx.x) * 4;
    if (base >= NE) return;                       // NE % 4 == 0 -> all 4 valid

    const int4 s4 = *(const int4*)(ei + base);
    const int4 d4 = *(const int4*)(ei + NE + base);

    // Issue all src-side gathers up front (one 32B sector per src).
    const float4 a0 = d_sp[s4.x].a, p0 = d_sp[s4.x].p;
    const float4 a1 = d_sp[s4.y].a, p1 = d_sp[s4.y].p;
    const float4 a2 = d_sp[s4.z].a, p2 = d_sp[s4.z].p;
    const float4 a3 = d_sp[s4.w].a, p3 = d_sp[s4.w].p;

    edge_one(d4.x, a0, p0);
    edge_one(d4.y, a1, p1);
    edge_one(d4.z, a2, p2);
    edge_one(d4.w, a3, p3);
}

// ---------------------------------------------------------------------------
// K4: finalize. out[n] = cb + sum_h num/(den + 1e-16)
// ---------------------------------------------------------------------------
__global__ void __launch_bounds__(256) k_final(float* __restrict__ out) {
    const int n = blockIdx.x * blockDim.x + threadIdx.x;
    if (n >= NN) return;
    const float4 d = d_den[n];
    const float4 u = d_num[n];
    out[n] = d_cb
           + u.x / (d.x + 1e-16f)
           + u.y / (d.y + 1e-16f)
           + u.z / (d.z + 1e-16f)
           + u.w / (d.w + 1e-16f);
}

extern "C" void kernel_launch(void* const* d_in, const int* in_sizes, int n_in,
                              void* d_out, int out_size) {
    const float* x       = (const float*)d_in[0];
    const int*   ei      = (const int*)d_in[1];
    const float* lin_w   = (const float*)d_in[2];
    const float* att_src = (const float*)d_in[3];
    const float* att_dst = (const float*)d_in[4];
    const float* bias    = (const float*)d_in[5];
    const float* fc_w    = (const float*)d_in[6];
    const float* fc_b    = (const float*)d_in[7];
    float* out = (float*)d_out;

    k_pre  <<<13, 256>>>(lin_w, att_src, att_dst, bias, fc_w, fc_b);
    k_proj <<<NN / 32, 128>>>(x);                     // 3125 blocks, 32 nodes each
    k_edge <<<(NE / 4 + 255) / 256, 256>>>(ei);       // 4 edges per thread
    k_final<<<(NN + 255) / 256, 256>>>(out);
}

// round 8
// speedup vs baseline: 1.7841x; 1.0013x over previous
#include <cuda_runtime.h>

#define NN 100000
#define NE 1600000
#define FIN 256
#define NH 4
#define NC 64

struct __align__(32) SP { float4 a; float4 p; };   // src-side: a_src + p, one 32B sector

// Scratch (static __device__ — no allocations allowed)
__device__ float  d_W[12 * FIN];   // 12 folded weight vectors: [as0..3, ad0..3, p0..3]
__device__ float  d_cb;            // bias . fc_w + fc_b
__device__ SP     d_sp[NN];        // packed a_src + p
__device__ float4 d_ad[NN];        // per-node a_dst, 4 heads
__device__ float4 d_den[NN];       // softmax denominators per head
__device__ float4 d_num[NN];       // weighted numerators per head

// ---------------------------------------------------------------------------
// K1: fold lin_w with (att_src, att_dst, fc_w) into 12 x 256 vectors + cb.
// ---------------------------------------------------------------------------
__global__ void k_pre(const float* __restrict__ lin_w,
                      const float* __restrict__ att_src,
                      const float* __restrict__ att_dst,
                      const float* __restrict__ bias,
                      const float* __restrict__ fc_w,
                      const float* __restrict__ fc_b) {
    const int j = blockIdx.x;
    const int k = threadIdx.x;   // 0..255 (feature dim)
    if (j < 12) {
        const int g = j >> 2;    // 0 = att_src, 1 = att_dst, 2 = fc_w
        const int h = j & 3;
        const float* coef = (g == 0) ? att_src + h * NC
                          : (g == 1) ? att_dst + h * NC
                                     : fc_w   + h * NC;
        const float* lw = lin_w + (size_t)h * NC * FIN + k;
        float acc = 0.f;
#pragma unroll 8
        for (int c = 0; c < NC; ++c)
            acc += coef[c] * lw[(size_t)c * FIN];
        d_W[j * FIN + k] = acc;
    } else {
        __shared__ float red[256];
        red[k] = bias[k] * fc_w[k];
        __syncthreads();
        for (int s = 128; s; s >>= 1) {
            if (k < s) red[k] += red[k + s];
            __syncthreads();
        }
        if (k == 0) d_cb = red[0] + fc_b[0];
    }
}

// ---------------------------------------------------------------------------
// K2: per-node projections, smem-staged, 2 nodes per thread. (unchanged from
// the 76.3us version)
// ---------------------------------------------------------------------------
__global__ void __launch_bounds__(128) k_proj(const float* __restrict__ x) {
    __shared__ float xs[32][264];
    __shared__ float ws[12 * FIN];

    const int tid = threadIdx.x;
    const int nb  = blockIdx.x * 32;

#pragma unroll
    for (int i = 0; i < 24; ++i)
        ws[tid + i * 128] = d_W[tid + i * 128];

    {
        const float4* xg = (const float4*)(x + (size_t)nb * FIN);
#pragma unroll
        for (int i = 0; i < 16; ++i) {
            const int f4  = tid + i * 128;       // 0..2047
            const int row = f4 >> 6;
            const int c4  = f4 & 63;
            ((float4*)&xs[row][c4 * 4])[0] = xg[row * 64 + c4];
        }
    }
    __syncthreads();

    const int warp = tid >> 5;
    const int lane = tid & 31;
    const int g    = lane >> 3;
    const int s    = lane & 7;
    const int wb   = warp * 8;
    const int n0   = wb + g;
    const int n1   = wb + g + 4;

    float acc0[12], acc1[12];
#pragma unroll
    for (int j = 0; j < 12; ++j) { acc0[j] = 0.f; acc1[j] = 0.f; }

    const float* xr0 = xs[n0];
    const float* xr1 = xs[n1];
#pragma unroll 4
    for (int t = 0; t < 32; ++t) {
        const int k = t * 8 + s;
        const float xv0 = xr0[k];
        const float xv1 = xr1[k];
#pragma unroll
        for (int j = 0; j < 12; ++j) {
            const float w = ws[j * 256 + k];
            acc0[j] += xv0 * w;
            acc1[j] += xv1 * w;
        }
    }
#pragma unroll
    for (int j = 0; j < 12; ++j) {
        acc0[j] += __shfl_xor_sync(0xffffffffu, acc0[j], 4);
        acc0[j] += __shfl_xor_sync(0xffffffffu, acc0[j], 2);
        acc0[j] += __shfl_xor_sync(0xffffffffu, acc0[j], 1);
        acc1[j] += __shfl_xor_sync(0xffffffffu, acc1[j], 4);
        acc1[j] += __shfl_xor_sync(0xffffffffu, acc1[j], 2);
        acc1[j] += __shfl_xor_sync(0xffffffffu, acc1[j], 1);
    }
    if (s == 0) {
        const int nodeA = nb + n0;
        d_sp[nodeA].a = make_float4(acc0[0], acc0[1], acc0[2],  acc0[3]);
        d_ad[nodeA]   = make_float4(acc0[4], acc0[5], acc0[6],  acc0[7]);
        d_sp[nodeA].p = make_float4(acc0[8], acc0[9], acc0[10], acc0[11]);
        d_den[nodeA]  = make_float4(0.f, 0.f, 0.f, 0.f);
        d_num[nodeA]  = make_float4(0.f, 0.f, 0.f, 0.f);

        const int nodeB = nb + n1;
        d_sp[nodeB].a = make_float4(acc1[0], acc1[1], acc1[2],  acc1[3]);
        d_ad[nodeB]   = make_float4(acc1[4], acc1[5], acc1[6],  acc1[7]);
        d_sp[nodeB].p = make_float4(acc1[8], acc1[9], acc1[10], acc1[11]);
        d_den[nodeB]  = make_float4(0.f, 0.f, 0.f, 0.f);
        d_num[nodeB]  = make_float4(0.f, 0.f, 0.f, 0.f);
    }
}

// ---------------------------------------------------------------------------
// K3: edge pass, 4 edges per thread, STRICT 3-phase schedule:
//   phase 1: ALL 12 gathers issued back-to-back (MLP ~12; nothing can be
//            hoisted across REDs by the compiler because of the "memory"
//            clobber, so the phases are laid out explicitly)
//   phase 2: all exp/leaky math
//   phase 3: all 8 REDs
// ---------------------------------------------------------------------------
__global__ void __launch_bounds__(256) k_edge(const int* __restrict__ ei) {
    const int base = (blockIdx.x * 256 + threadIdx.x) * 4;
    if (base >= NE) return;                       // NE % 4 == 0 -> all 4 valid

    const int4 s4 = *(const int4*)(ei + base);
    const int4 d4 = *(const int4*)(ei + NE + base);
    const int srcs[4] = { s4.x, s4.y, s4.z, s4.w };
    const int dsts[4] = { d4.x, d4.y, d4.z, d4.w };

    // phase 1: all gathers
    float4 a[4], p[4], b[4];
#pragma unroll
    for (int i = 0; i < 4; ++i) { a[i] = d_sp[srcs[i]].a; p[i] = d_sp[srcs[i]].p; }
#pragma unroll
    for (int i = 0; i < 4; ++i) b[i] = d_ad[dsts[i]];

    // phase 2: all math
    float4 ex[4], np[4];
#pragma unroll
    for (int i = 0; i < 4; ++i) {
        float t;
        t = a[i].x + b[i].x; t = t > 0.f ? t : 0.2f * t; ex[i].x = __expf(t);
        t = a[i].y + b[i].y; t = t > 0.f ? t : 0.2f * t; ex[i].y = __expf(t);
        t = a[i].z + b[i].z; t = t > 0.f ? t : 0.2f * t; ex[i].z = __expf(t);
        t = a[i].w + b[i].w; t = t > 0.f ? t : 0.2f * t; ex[i].w = __expf(t);
        np[i].x = ex[i].x * p[i].x; np[i].y = ex[i].y * p[i].y;
        np[i].z = ex[i].z * p[i].z; np[i].w = ex[i].w * p[i].w;
    }

    // phase 3: all REDs
#pragma unroll
    for (int i = 0; i < 4; ++i) {
        asm volatile("red.global.add.v4.f32 [%0], {%1,%2,%3,%4};"
                     :: "l"(&d_den[dsts[i]]),
                        "f"(ex[i].x), "f"(ex[i].y), "f"(ex[i].z), "f"(ex[i].w)
                     : "memory");
    }
#pragma unroll
    for (int i = 0; i < 4; ++i) {
        asm volatile("red.global.add.v4.f32 [%0], {%1,%2,%3,%4};"
                     :: "l"(&d_num[dsts[i]]),
                        "f"(np[i].x), "f"(np[i].y), "f"(np[i].z), "f"(np[i].w)
                     : "memory");
    }
}

// ---------------------------------------------------------------------------
// K4: finalize. out[n] = cb + sum_h num/(den + 1e-16)
// ---------------------------------------------------------------------------
__global__ void __launch_bounds__(256) k_final(float* __restrict__ out) {
    const int n = blockIdx.x * blockDim.x + threadIdx.x;
    if (n >= NN) return;
    const float4 d = d_den[n];
    const float4 u = d_num[n];
    out[n] = d_cb
           + u.x / (d.x + 1e-16f)
           + u.y / (d.y + 1e-16f)
           + u.z / (d.z + 1e-16f)
           + u.w / (d.w + 1e-16f);
}

extern "C" void kernel_launch(void* const* d_in, const int* in_sizes, int n_in,
                              void* d_out, int out_size) {
    const float* x       = (const float*)d_in[0];
    const int*   ei      = (const int*)d_in[1];
    const float* lin_w   = (const float*)d_in[2];
    const float* att_src = (const float*)d_in[3];
    const float* att_dst = (const float*)d_in[4];
    const float* bias    = (const float*)d_in[5];
    const float* fc_w    = (const float*)d_in[6];
    const float* fc_b    = (const float*)d_in[7];
    float* out = (float*)d_out;

    k_pre  <<<13, 256>>>(lin_w, att_src, att_dst, bias, fc_w, fc_b);
    k_proj <<<NN / 32, 128>>>(x);                     // 3125 blocks, 32 nodes each
    k_edge <<<(NE / 4 + 255) / 256, 256>>>(ei);       // 4 edges per thread
    k_final<<<(NN + 255) / 256, 256>>>(out);
}